// round 11
// baseline (speedup 1.0000x reference)
#include <cuda_runtime.h>
#include <cuda_bf16.h>

// MultiScaleEdgeBuilder: B=64 graphs x 256 nodes.
// E = 64 * 256*255 = 4,177,920 ordered intra-graph pairs.
// Output layout (float32, concatenated flattened reference outputs):
//   [0,        2E)  edge_index  [2,E]  (row block then col block)
//   [2E,      18E)  edge_attr   [E,16] zeros
//   [18E,     21E)  rbf         [E,3]  exp(-(d/c)^2), c in {4,8,12}
//
// rbf trick: r = exp(-d2/576) -> {r^36, r^9, r^4}: 1 MUFU + 7 FMUL per edge.
// R6: zeros block (76% of bytes) now written with 256-bit streaming stores
//     (st.global.cs.v8.b32 -> STG.E.256, sm_100+) in a BLOCK-CONTIGUOUS slab
//     (64KB/block) instead of 16 chip-wide strided streams: fewer store ops
//     (21->13/thread), half the L1 wavefronts on the dominant stream, and
//     sequential DRAM bursts on writeback.

namespace {
constexpr int NPER   = 256;
constexpr int NGRAPH = 64;
constexpr int PAIRS  = NPER * (NPER - 1);   // 65280  (divisible by 4)
constexpr int E      = NGRAPH * PAIRS;      // 4177920
constexpr int Q      = E / 4;               // 1044480 threads, 4 edges each
constexpr int NTHR   = 256;
constexpr int NBLK   = Q / NTHR;            // 4080 exactly
}

__device__ __forceinline__ void stg256_zero(void* p) {
    asm volatile("st.global.cs.v8.b32 [%0], {%1,%1,%1,%1,%1,%1,%1,%1};"
                 :: "l"(p), "r"(0) : "memory");
}

__global__ __launch_bounds__(NTHR) void edge_builder_kernel(
    const float* __restrict__ pos, float* __restrict__ out)
{
    const int tid = threadIdx.x;
    const int blk = blockIdx.x;
    const int idx = blk * NTHR + tid;                 // [0, Q)
    const int e0  = idx * 4;

    // All 4 edges of this thread live in the same graph (PAIRS % 4 == 0).
    const int g    = e0 / PAIRS;
    const int p0   = e0 - g * PAIRS;
    const int base = g * NPER;

    float rowv[4], colv[4], rb[12];

#pragma unroll
    for (int k = 0; k < 4; ++k) {
        const int p  = p0 + k;
        const int ia = p / 255;           // constant division -> mul/shift
        const int r  = p - ia * 255;
        const int ib = r + (r >= ia ? 1 : 0);
        const int rowi = base + ia;
        const int coli = base + ib;
        rowv[k] = (float)rowi;
        colv[k] = (float)coli;

        const float dx = __ldg(&pos[3 * rowi + 0]) - __ldg(&pos[3 * coli + 0]);
        const float dy = __ldg(&pos[3 * rowi + 1]) - __ldg(&pos[3 * coli + 1]);
        const float dz = __ldg(&pos[3 * rowi + 2]) - __ldg(&pos[3 * coli + 2]);
        const float d2 = dx * dx + dy * dy + dz * dz;

        const float rbse = __expf(-d2 * (1.0f / 576.0f));
        const float r2  = rbse * rbse;
        const float r4  = r2 * r2;
        const float r8  = r4 * r4;
        const float r9  = r8 * rbse;
        const float r16 = r8 * r8;
        const float r32 = r16 * r16;
        const float r36 = r32 * r4;
        rb[3 * k + 0] = r36;   // exp(-d2/16)   cutoff 4
        rb[3 * k + 1] = r9;    // exp(-d2/64)   cutoff 8
        rb[3 * k + 2] = r4;    // exp(-d2/144)  cutoff 12
    }

    // ---- edge_index: 128-bit streaming stores, line-complete ----
    float4* __restrict__ orow = reinterpret_cast<float4*>(out);
    float4* __restrict__ ocol = reinterpret_cast<float4*>(out + (size_t)E);
    __stcs(&orow[idx], make_float4(rowv[0], rowv[1], rowv[2], rowv[3]));
    __stcs(&ocol[idx], make_float4(colv[0], colv[1], colv[2], colv[3]));

    // ---- edge_attr zeros: 16E floats = 2E 32B-units. Block-contiguous slab:
    //      block owns [blk*2048, (blk+1)*2048) 32B-units = 64KB contiguous.
    //      Each warp store = 1KB contiguous, 8 x STG.E.256.CS per thread. ----
    {
        char* __restrict__ ozb = reinterpret_cast<char*>(out + 2 * (size_t)E);
        char* p = ozb + ((size_t)blk * (NTHR * 8) + tid) * 32;
#pragma unroll
        for (int k = 0; k < 8; ++k) {
            stg256_zero(p);
            p += NTHR * 32;                           // 8KB stride, warp-coalesced
        }
    }

    // ---- rbf [E,3]: 12 contiguous floats per thread = 3 x STG.128.CS ----
    float4* __restrict__ orbf = reinterpret_cast<float4*>(out + 18 * (size_t)E);
    __stcs(&orbf[3 * (size_t)idx + 0], make_float4(rb[0], rb[1], rb[2],  rb[3]));
    __stcs(&orbf[3 * (size_t)idx + 1], make_float4(rb[4], rb[5], rb[6],  rb[7]));
    __stcs(&orbf[3 * (size_t)idx + 2], make_float4(rb[8], rb[9], rb[10], rb[11]));
}

extern "C" void kernel_launch(void* const* d_in, const int* in_sizes, int n_in,
                              void* d_out, int out_size)
{
    const float* pos = (const float*)d_in[0];   // [N,3] float32
    float* out = (float*)d_out;                 // 21*E float32
    edge_builder_kernel<<<NBLK, NTHR>>>(pos, out);
}

// round 12
// speedup vs baseline: 1.0046x; 1.0046x over previous
#include <cuda_runtime.h>
#include <cuda_bf16.h>

// MultiScaleEdgeBuilder: B=64 graphs x 256 nodes.
// E = 64 * 256*255 = 4,177,920 ordered intra-graph pairs.
// Output layout (float32, concatenated flattened reference outputs):
//   [0,        2E)  edge_index  [2,E]  (row block then col block)
//   [2E,      18E)  edge_attr   [E,16] zeros
//   [18E,     21E)  rbf         [E,3]  exp(-(d/c)^2), c in {4,8,12}
//
// rbf trick: r = exp(-d2/576) -> {r^36, r^9, r^4}: 1 MUFU + 7 FMUL per edge.
// R11: loads were ~2x the store wavefronts in l1tex (24 scalar LDG/thread,
//      col gather ~12 lines each). Repack pos[N,3] -> float4[N] in a tiny
//      prologue kernel, then gather with LDG.128: 8 wide loads/thread,
//      ~76 load wf/warp instead of ~170. Stores identical to R5 (best).

namespace {
constexpr int NPER   = 256;
constexpr int NGRAPH = 64;
constexpr int NTOT   = NGRAPH * NPER;       // 16384
constexpr int PAIRS  = NPER * (NPER - 1);   // 65280  (divisible by 4)
constexpr int E      = NGRAPH * PAIRS;      // 4177920
constexpr int Q      = E / 4;               // 1044480 threads, 4 edges each
constexpr int NTHR   = 256;
constexpr int NBLK   = Q / NTHR;            // 4080 exactly
}

__device__ float4 g_pos4[NTOT];             // padded pos, 256 KB scratch

__global__ __launch_bounds__(NTHR) void repack_kernel(const float* __restrict__ pos)
{
    const int i = blockIdx.x * NTHR + threadIdx.x;
    if (i < NTOT)
        g_pos4[i] = make_float4(pos[3 * i + 0], pos[3 * i + 1], pos[3 * i + 2], 0.f);
}

__global__ __launch_bounds__(NTHR) void edge_builder_kernel(float* __restrict__ out)
{
    const int idx = blockIdx.x * NTHR + threadIdx.x;   // [0, Q)
    const int e0  = idx * 4;

    // All 4 edges of this thread live in the same graph (PAIRS % 4 == 0).
    const int g    = e0 / PAIRS;
    const int p0   = e0 - g * PAIRS;
    const int base = g * NPER;

    float rowv[4], colv[4], rb[12];

#pragma unroll
    for (int k = 0; k < 4; ++k) {
        const int p  = p0 + k;
        const int ia = p / 255;           // constant division -> mul/shift
        const int r  = p - ia * 255;
        const int ib = r + (r >= ia ? 1 : 0);
        const int rowi = base + ia;
        const int coli = base + ib;
        rowv[k] = (float)rowi;
        colv[k] = (float)coli;

        const float4 pa = __ldg(&g_pos4[rowi]);   // LDG.128, near-broadcast
        const float4 pb = __ldg(&g_pos4[coli]);   // LDG.128 gather
        const float dx = pa.x - pb.x;
        const float dy = pa.y - pb.y;
        const float dz = pa.z - pb.z;
        const float d2 = dx * dx + dy * dy + dz * dz;

        const float rbse = __expf(-d2 * (1.0f / 576.0f));
        const float r2  = rbse * rbse;
        const float r4  = r2 * r2;
        const float r8  = r4 * r4;
        const float r9  = r8 * rbse;
        const float r16 = r8 * r8;
        const float r32 = r16 * r16;
        const float r36 = r32 * r4;
        rb[3 * k + 0] = r36;   // exp(-d2/16)   cutoff 4
        rb[3 * k + 1] = r9;    // exp(-d2/64)   cutoff 8
        rb[3 * k + 2] = r4;    // exp(-d2/144)  cutoff 12
    }

    // ---- Stores: R5 layout, all 128-bit streaming, line-complete ----
    float4* __restrict__ orow = reinterpret_cast<float4*>(out);
    float4* __restrict__ ocol = reinterpret_cast<float4*>(out + (size_t)E);
    __stcs(&orow[idx], make_float4(rowv[0], rowv[1], rowv[2], rowv[3]));
    __stcs(&ocol[idx], make_float4(colv[0], colv[1], colv[2], colv[3]));

    // edge_attr zeros: 16E floats = 4E float4, strided so each of the 16
    // stores per thread is warp-coalesced (stride Q between k's).
    float4* __restrict__ oz = reinterpret_cast<float4*>(out + 2 * (size_t)E);
    const float4 z4 = make_float4(0.f, 0.f, 0.f, 0.f);
#pragma unroll
    for (int k = 0; k < 16; ++k)
        __stcs(&oz[(size_t)k * Q + idx], z4);

    // rbf [E,3]: 12 contiguous floats per thread = 3 float4
    float4* __restrict__ orbf = reinterpret_cast<float4*>(out + 18 * (size_t)E);
    __stcs(&orbf[3 * (size_t)idx + 0], make_float4(rb[0], rb[1], rb[2],  rb[3]));
    __stcs(&orbf[3 * (size_t)idx + 1], make_float4(rb[4], rb[5], rb[6],  rb[7]));
    __stcs(&orbf[3 * (size_t)idx + 2], make_float4(rb[8], rb[9], rb[10], rb[11]));
}

extern "C" void kernel_launch(void* const* d_in, const int* in_sizes, int n_in,
                              void* d_out, int out_size)
{
    const float* pos = (const float*)d_in[0];   // [N,3] float32
    float* out = (float*)d_out;                 // 21*E float32
    repack_kernel<<<(NTOT + NTHR - 1) / NTHR, NTHR>>>(pos);
    edge_builder_kernel<<<NBLK, NTHR>>>(out);
}

// round 14
// speedup vs baseline: 1.0423x; 1.0375x over previous
#include <cuda_runtime.h>
#include <cuda_bf16.h>
#include <cstdint>

// MultiScaleEdgeBuilder: B=64 graphs x 256 nodes.
// E = 64 * 256*255 = 4,177,920 ordered intra-graph pairs.
// Output layout (float32, concatenated flattened reference outputs):
//   [0,        2E)  edge_index  [2,E]  (row block then col block)
//   [2E,      18E)  edge_attr   [E,16] zeros
//   [18E,     21E)  rbf         [E,3]  exp(-(d/c)^2), c in {4,8,12}
//
// rbf trick: r = exp(-d2/576) -> {r^36, r^9, r^4}: 1 MUFU + 7 FMUL per edge.
// R13: retry of R12's L2-pinning theory with the legal encoding. Bare
//      .L2::evict_last requires v8.b32 on this ptxas; instead use
//      createpolicy.fractional.L2::evict_last + st.global.L2::cache_hint
//      (valid for v4.f32). Pin edge_index+rbf (80MB) so back-to-back graph
//      replays rewrite those lines in L2 instead of draining to DRAM;
//      stream the 256MB zeros with .CS (evict-first) so they can't
//      displace the pinned set.

namespace {
constexpr int NPER   = 256;
constexpr int NGRAPH = 64;
constexpr int PAIRS  = NPER * (NPER - 1);   // 65280  (divisible by 4)
constexpr int E      = NGRAPH * PAIRS;      // 4177920
constexpr int Q      = E / 4;               // 1044480 threads, 4 edges each
constexpr int NTHR   = 256;
constexpr int NBLK   = Q / NTHR;            // 4080 exactly
}

__device__ __forceinline__ uint64_t policy_evict_last() {
    uint64_t pol;
    asm("createpolicy.fractional.L2::evict_last.b64 %0, 1.0;" : "=l"(pol));
    return pol;
}

__device__ __forceinline__ void st128_pin(float4* p, float4 v, uint64_t pol) {
    asm volatile("st.global.L2::cache_hint.v4.f32 [%0], {%1,%2,%3,%4}, %5;"
                 :: "l"(p), "f"(v.x), "f"(v.y), "f"(v.z), "f"(v.w), "l"(pol)
                 : "memory");
}

__global__ __launch_bounds__(NTHR) void edge_builder_kernel(
    const float* __restrict__ pos, float* __restrict__ out)
{
    const int idx = blockIdx.x * NTHR + threadIdx.x;   // [0, Q)
    const int e0  = idx * 4;

    // All 4 edges of this thread live in the same graph (PAIRS % 4 == 0).
    const int g    = e0 / PAIRS;
    const int p0   = e0 - g * PAIRS;
    const int base = g * NPER;

    float rowv[4], colv[4], rb[12];

#pragma unroll
    for (int k = 0; k < 4; ++k) {
        const int p  = p0 + k;
        const int ia = p / 255;           // constant division -> mul/shift
        const int r  = p - ia * 255;
        const int ib = r + (r >= ia ? 1 : 0);
        const int rowi = base + ia;
        const int coli = base + ib;
        rowv[k] = (float)rowi;
        colv[k] = (float)coli;

        const float dx = __ldg(&pos[3 * rowi + 0]) - __ldg(&pos[3 * coli + 0]);
        const float dy = __ldg(&pos[3 * rowi + 1]) - __ldg(&pos[3 * coli + 1]);
        const float dz = __ldg(&pos[3 * rowi + 2]) - __ldg(&pos[3 * coli + 2]);
        const float d2 = dx * dx + dy * dy + dz * dz;

        const float rbse = __expf(-d2 * (1.0f / 576.0f));
        const float r2  = rbse * rbse;
        const float r4  = r2 * r2;
        const float r8  = r4 * r4;
        const float r9  = r8 * rbse;
        const float r16 = r8 * r8;
        const float r32 = r16 * r16;
        const float r36 = r32 * r4;
        rb[3 * k + 0] = r36;   // exp(-d2/16)   cutoff 4
        rb[3 * k + 1] = r9;    // exp(-d2/64)   cutoff 8
        rb[3 * k + 2] = r4;    // exp(-d2/144)  cutoff 12
    }

    const uint64_t pol = policy_evict_last();

    // ---- edge_index: pinned in L2 across replays (evict_last policy) ----
    float4* __restrict__ orow = reinterpret_cast<float4*>(out);
    float4* __restrict__ ocol = reinterpret_cast<float4*>(out + (size_t)E);
    st128_pin(&orow[idx], make_float4(rowv[0], rowv[1], rowv[2], rowv[3]), pol);
    st128_pin(&ocol[idx], make_float4(colv[0], colv[1], colv[2], colv[3]), pol);

    // ---- edge_attr zeros: 256MB stream, evict-first so it can't displace
    //      the pinned 80MB. 16 warp-coalesced STG.128.CS per thread. ----
    float4* __restrict__ oz = reinterpret_cast<float4*>(out + 2 * (size_t)E);
    const float4 z4 = make_float4(0.f, 0.f, 0.f, 0.f);
#pragma unroll
    for (int k = 0; k < 16; ++k)
        __stcs(&oz[(size_t)k * Q + idx], z4);

    // ---- rbf [E,3]: pinned in L2 across replays (evict_last policy) ----
    float4* __restrict__ orbf = reinterpret_cast<float4*>(out + 18 * (size_t)E);
    st128_pin(&orbf[3 * (size_t)idx + 0], make_float4(rb[0], rb[1], rb[2],  rb[3]),  pol);
    st128_pin(&orbf[3 * (size_t)idx + 1], make_float4(rb[4], rb[5], rb[6],  rb[7]),  pol);
    st128_pin(&orbf[3 * (size_t)idx + 2], make_float4(rb[8], rb[9], rb[10], rb[11]), pol);
}

extern "C" void kernel_launch(void* const* d_in, const int* in_sizes, int n_in,
                              void* d_out, int out_size)
{
    const float* pos = (const float*)d_in[0];   // [N,3] float32
    float* out = (float*)d_out;                 // 21*E float32
    edge_builder_kernel<<<NBLK, NTHR>>>(pos, out);
}